// round 7
// baseline (speedup 1.0000x reference)
#include <cuda_runtime.h>
#include <cuda_bf16.h>
#include <math.h>
#include <cstdint>

// Problem constants
#define Bsz   2
#define Sseq  2048
#define Dmod  2048
#define Hh    16
#define DKk   128
#define Ll    64
#define Mrows (Bsz * Sseq)   // 4096

// ---------------------------------------------------------------------------
// Device scratch
// ---------------------------------------------------------------------------
__device__ float    g_Q   [(size_t)Mrows * Dmod];
__device__ float    g_Ar  [(size_t)Mrows * Dmod];   // rounded queries / FA out
__device__ float    g_ArK [(size_t)Mrows * Dmod];
__device__ float    g_ArV [(size_t)Mrows * Dmod];
__device__ uint32_t g_Khi[(size_t)Mrows * 1024];    // [b,h,s][64 words]
__device__ uint32_t g_Klo[(size_t)Mrows * 1024];
__device__ uint32_t g_Vhi[(size_t)Mrows * 1024];    // [b,h,d][1024 words]
__device__ uint32_t g_Vlo[(size_t)Mrows * 1024];
__device__ float    g_WqT[(size_t)Dmod * Dmod];
__device__ float    g_WkT[(size_t)Dmod * Dmod];
__device__ float    g_WvT[(size_t)Dmod * Dmod];
__device__ float    g_WoT[(size_t)Dmod * Dmod];
__device__ float    g_bk[Dmod];
__device__ float    g_bv[Dmod];

// ---------------------------------------------------------------------------
// Helpers
// ---------------------------------------------------------------------------
__device__ __forceinline__ uint32_t smem_u32(const void* p) {
    uint32_t a;
    asm("{ .reg .u64 t; cvta.to.shared.u64 t, %1; cvt.u32.u64 %0, t; }"
        : "=r"(a) : "l"(p));
    return a;
}

#define CP_ASYNC16(dst, src) \
    asm volatile("cp.async.cg.shared.global [%0], [%1], 16;" \
        :: "r"((uint32_t)(dst)), "l"(src) : "memory")
#define CP_COMMIT() asm volatile("cp.async.commit_group;" ::: "memory")
#define CP_WAIT(n)  asm volatile("cp.async.wait_group %0;" :: "n"(n) : "memory")

__device__ __forceinline__ uint32_t f2tf32(float x) {
    uint32_t r;
    asm("cvt.rna.tf32.f32 %0, %1;" : "=r"(r) : "f"(x));
    return r;
}

// k-permutation within 16-element blocks: q = 4*(r&3) + (r>>2)
__device__ __forceinline__ int perm16(int k) {
    const int r = k & 15;
    return (k & ~15) | (4 * (r & 3) + (r >> 2));
}

__device__ __forceinline__ void mma_tf32(float* c, const uint32_t* a, const uint32_t* b) {
    asm volatile(
        "mma.sync.aligned.m16n8k8.row.col.f32.tf32.tf32.f32 "
        "{%0,%1,%2,%3}, {%4,%5,%6,%7}, {%8,%9}, {%0,%1,%2,%3};"
        : "+f"(c[0]), "+f"(c[1]), "+f"(c[2]), "+f"(c[3])
        : "r"(a[0]), "r"(a[1]), "r"(a[2]), "r"(a[3]), "r"(b[0]), "r"(b[1]));
}

__device__ __forceinline__ void mma_bf16(float* c, const uint32_t* a,
                                         uint32_t b0, uint32_t b1) {
    asm volatile(
        "mma.sync.aligned.m16n8k16.row.col.f32.bf16.bf16.f32 "
        "{%0,%1,%2,%3}, {%4,%5,%6,%7}, {%8,%9}, {%0,%1,%2,%3};"
        : "+f"(c[0]), "+f"(c[1]), "+f"(c[2]), "+f"(c[3])
        : "r"(a[0]), "r"(a[1]), "r"(a[2]), "r"(a[3]), "r"(b0), "r"(b1));
}

__device__ __forceinline__ uint32_t packbf(float e0, float e1) {
    uint32_t r;
    asm("cvt.rn.bf16x2.f32 %0, %1, %2;" : "=r"(r) : "f"(e1), "f"(e0));
    return r;
}

__device__ __forceinline__ void split2(float e0, float e1,
                                       uint32_t& hi, uint32_t& lo) {
    hi = packbf(e0, e1);
    float r0 = e0 - __uint_as_float(hi << 16);
    float r1 = e1 - __uint_as_float(hi & 0xFFFF0000u);
    lo = packbf(r0, r1);
}

__device__ __forceinline__ float ex2(float x) {
    float y;
    asm("ex2.approx.ftz.f32 %0, %1;" : "=f"(y) : "f"(x));
    return y;
}

// ---------------------------------------------------------------------------
// Round activations to tf32 + perm16, merged over 3 inputs (grid.z).
// 16 elems / thread. out[q] <- in[k]: out4[j] = (a[j], b[j], c[j], d[j]).
// ---------------------------------------------------------------------------
__global__ __launch_bounds__(256) void round_perm_kernel(
    const float* __restrict__ in0, const float* __restrict__ in1,
    const float* __restrict__ in2,
    float* __restrict__ o0, float* __restrict__ o1, float* __restrict__ o2)
{
    const int z = blockIdx.z;
    const float* in = (z == 0) ? in0 : (z == 1) ? in1 : in2;
    float* out = (z == 0) ? o0 : (z == 1) ? o1 : o2;

    const size_t base = ((size_t)blockIdx.x * 256 + threadIdx.x) * 16;
    const float4 a = *(const float4*)(in + base);
    const float4 b = *(const float4*)(in + base + 4);
    const float4 c = *(const float4*)(in + base + 8);
    const float4 d = *(const float4*)(in + base + 12);
    float4 o;
    o = make_float4(__uint_as_float(f2tf32(a.x)), __uint_as_float(f2tf32(b.x)),
                    __uint_as_float(f2tf32(c.x)), __uint_as_float(f2tf32(d.x)));
    *(float4*)(out + base) = o;
    o = make_float4(__uint_as_float(f2tf32(a.y)), __uint_as_float(f2tf32(b.y)),
                    __uint_as_float(f2tf32(c.y)), __uint_as_float(f2tf32(d.y)));
    *(float4*)(out + base + 4) = o;
    o = make_float4(__uint_as_float(f2tf32(a.z)), __uint_as_float(f2tf32(b.z)),
                    __uint_as_float(f2tf32(c.z)), __uint_as_float(f2tf32(d.z)));
    *(float4*)(out + base + 8) = o;
    o = make_float4(__uint_as_float(f2tf32(a.w)), __uint_as_float(f2tf32(b.w)),
                    __uint_as_float(f2tf32(c.w)), __uint_as_float(f2tf32(d.w)));
    *(float4*)(out + base + 12) = o;
}

// ---------------------------------------------------------------------------
// Fused fold + transpose (merged z over K/V weights):
// WT[h*128+c][d] = sum_l Wl[d][h*64+l] * Wr[l][c], tf32-rounded, perm16 on d.
// ---------------------------------------------------------------------------
#define FT_SMEM_BYTES ((64 * 132 + 64 * 128) * 4)

__global__ __launch_bounds__(256) void foldT_kernel(
    const float* __restrict__ Wl0, const float* __restrict__ Wr0,
    float* __restrict__ WT0,
    const float* __restrict__ Wl1, const float* __restrict__ Wr1,
    float* __restrict__ WT1)
{
    const float* Wl = blockIdx.z ? Wl1 : Wl0;
    const float* Wr = blockIdx.z ? Wr1 : Wr0;
    float* WT = blockIdx.z ? WT1 : WT0;

    extern __shared__ float fsm[];
    float* sWl = fsm;             // [l][132]
    float* sWr = fsm + 64 * 132;  // [l][128]

    const int dblk = blockIdx.x;
    const int h    = blockIdx.y;
    const int t    = threadIdx.x;

    #pragma unroll
    for (int i = 0; i < 8; i++) {
        int u = t + i * 256;
        int l = u >> 5, c4 = u & 31;
        *(float4*)&sWr[l * 128 + c4 * 4] = *(const float4*)(Wr + l * DKk + c4 * 4);
    }
    #pragma unroll
    for (int i = 0; i < 8; i++) {
        int u = t + i * 256;
        int d = u >> 4, l4 = u & 15;
        float4 x = *(const float4*)(Wl + (size_t)(dblk * 128 + d) * (Hh * Ll)
                                    + h * Ll + l4 * 4);
        sWl[(l4 * 4 + 0) * 132 + d] = x.x;
        sWl[(l4 * 4 + 1) * 132 + d] = x.y;
        sWl[(l4 * 4 + 2) * 132 + d] = x.z;
        sWl[(l4 * 4 + 3) * 132 + d] = x.w;
    }
    __syncthreads();

    const int d8 = (t & 15) * 8;
    const int cg = t >> 4;
    float acc[8][8];
    #pragma unroll
    for (int dd = 0; dd < 8; dd++)
        #pragma unroll
        for (int j = 0; j < 8; j++) acc[dd][j] = 0.f;

    for (int l = 0; l < Ll; l++) {
        float4 a0 = *(float4*)&sWl[l * 132 + d8];
        float4 a1 = *(float4*)&sWl[l * 132 + d8 + 4];
        const float* wr = &sWr[l * 128 + cg * 8];
        #pragma unroll
        for (int j = 0; j < 8; j++) {
            float wv = wr[j];
            acc[0][j] += a0.x * wv;
            acc[1][j] += a0.y * wv;
            acc[2][j] += a0.z * wv;
            acc[3][j] += a0.w * wv;
            acc[4][j] += a1.x * wv;
            acc[5][j] += a1.y * wv;
            acc[6][j] += a1.z * wv;
            acc[7][j] += a1.w * wv;
        }
    }

    // store with perm16 on d: pos(d8+i2)=4*i2+off, pos(d8+i2+4)=4*i2+off+1
    const int dbase = d8 & ~8;
    const int off   = (d8 & 8) ? 2 : 0;
    #pragma unroll
    for (int j = 0; j < 8; j++) {
        const int n = h * 128 + cg * 8 + j;
        float* dst = WT + (size_t)n * Dmod + dblk * 128 + dbase + off;
        #pragma unroll
        for (int i2 = 0; i2 < 4; i2++) {
            float2 v = make_float2(__uint_as_float(f2tf32(acc[i2][j])),
                                   __uint_as_float(f2tf32(acc[i2 + 4][j])));
            *(float2*)(dst + 4 * i2) = v;
        }
    }
}

__global__ __launch_bounds__(128) void fold_b_kernel(
    const float* __restrict__ bl0, const float* __restrict__ Wr0,
    const float* __restrict__ br0, float* __restrict__ be0,
    const float* __restrict__ bl1, const float* __restrict__ Wr1,
    const float* __restrict__ br1, float* __restrict__ be1)
{
    const float* bl = blockIdx.y ? bl1 : bl0;
    const float* Wr = blockIdx.y ? Wr1 : Wr0;
    const float* br = blockIdx.y ? br1 : br0;
    float* beff = blockIdx.y ? be1 : be0;
    const int h = blockIdx.x;
    const int c = threadIdx.x;
    float acc = br[c];
    #pragma unroll 16
    for (int l = 0; l < Ll; l++)
        acc += bl[h * Ll + l] * Wr[l * DKk + c];
    beff[h * DKk + c] = acc;
}

// ---------------------------------------------------------------------------
// 32x32 tiled transpose + tf32 round + perm16 (merged z over Wq/Wo)
// ---------------------------------------------------------------------------
__global__ __launch_bounds__(256) void transpose_kernel(
    const float* __restrict__ in0, float* __restrict__ out0,
    const float* __restrict__ in1, float* __restrict__ out1)
{
    const float* in = blockIdx.z ? in1 : in0;
    float* out = blockIdx.z ? out1 : out0;
    __shared__ float tile[32][33];
    const int bx = blockIdx.x * 32;
    const int by = blockIdx.y * 32;
    const int tx = threadIdx.x & 31;
    const int ty = threadIdx.x >> 5;
    #pragma unroll
    for (int i = 0; i < 32; i += 8)
        tile[ty + i][tx] = in[(size_t)(by + ty + i) * Dmod + bx + tx];
    __syncthreads();
    const int ktx = perm16(tx);
    #pragma unroll
    for (int i = 0; i < 32; i += 8)
        out[(size_t)(bx + ty + i) * Dmod + by + ktx] =
            __uint_as_float(f2tf32(tile[tx][ty + i]));
}

// ---------------------------------------------------------------------------
// Tensor-core tf32 GEMM body: C = A @ WT^T + bias. A/WT pre-rounded+perm16.
// LDS.128 fragment loads (one per two k8 steps). Stride 48 (conflict-free).
// MODE 0: fp32 out. MODE 1: K split planes. MODE 2: V split planes transposed.
// ---------------------------------------------------------------------------
#define G_BK 32
#define G_NK (Dmod / G_BK)
#define G_STRIDE 48
#define G_OP_WORDS (128 * G_STRIDE)         // 6144
#define G_STAGE_WORDS (2 * G_OP_WORDS)      // 12288
#define G_SMEM_BYTES (2 * G_STAGE_WORDS * 4)  // 98304

template<int MODE>
__device__ __forceinline__ void gemm_body(
    uint32_t* smw, uint32_t smem_base,
    const float* __restrict__ A, const float* __restrict__ WT,
    const float* __restrict__ bias, float* __restrict__ C,
    uint32_t* __restrict__ Chi, uint32_t* __restrict__ Clo,
    int m0, int n0)
{
    const int t    = threadIdx.x;
    const int wid  = t >> 5;
    const int lane = t & 31;
    const int g    = lane >> 2;
    const int tid4 = lane & 3;
    const int wm   = wid >> 2;
    const int wn   = wid & 3;

    float acc[4][4][4];
    #pragma unroll
    for (int mf = 0; mf < 4; mf++)
        #pragma unroll
        for (int nf = 0; nf < 4; nf++)
            #pragma unroll
            for (int r = 0; r < 4; r++) acc[mf][nf][r] = 0.f;

    auto load_stage = [&](int s, int k0) {
        const uint32_t aB = smem_base + (uint32_t)s * G_STAGE_WORDS * 4;
        const uint32_t bB = aB + G_OP_WORDS * 4;
        #pragma unroll
        for (int i = 0; i < 4; i++) {
            int u = t + i * 256;
            int row = u >> 3, c4 = u & 7;
            uint32_t off = (uint32_t)(row * G_STRIDE + c4 * 4) * 4;
            CP_ASYNC16(aB + off, A + (size_t)(m0 + row) * Dmod + k0 + c4 * 4);
        }
        #pragma unroll
        for (int i = 0; i < 4; i++) {
            int u = t + i * 256;
            int row = u >> 3, c4 = u & 7;
            uint32_t off = (uint32_t)(row * G_STRIDE + c4 * 4) * 4;
            CP_ASYNC16(bB + off, WT + (size_t)(n0 + row) * Dmod + k0 + c4 * 4);
        }
    };

    load_stage(0, 0);
    CP_COMMIT();
    load_stage(1, G_BK);
    CP_COMMIT();

    for (int k = 0; k < G_NK; k++) {
        const int s = k & 1;
        CP_WAIT(1);
        __syncthreads();

        const uint32_t* sA = smw + (size_t)s * G_STAGE_WORDS;
        const uint32_t* sB = sA + G_OP_WORDS;

        #pragma unroll
        for (int kb = 0; kb < 2; kb++) {
            const int kc = 16 * kb + 4 * tid4;
            uint4 aL[4], aH[4], bq[4];
            #pragma unroll
            for (int mf = 0; mf < 4; mf++) {
                const int r0 = wm * 64 + mf * 16;
                aL[mf] = *(const uint4*)&sA[(r0 + g) * G_STRIDE + kc];
                aH[mf] = *(const uint4*)&sA[(r0 + g + 8) * G_STRIDE + kc];
            }
            #pragma unroll
            for (int nf = 0; nf < 4; nf++)
                bq[nf] = *(const uint4*)&sB[(wn * 32 + nf * 8 + g) * G_STRIDE + kc];

            #pragma unroll
            for (int mf = 0; mf < 4; mf++) {
                uint32_t af[4] = {aL[mf].x, aH[mf].x, aL[mf].y, aH[mf].y};
                #pragma unroll
                for (int nf = 0; nf < 4; nf++) {
                    uint32_t bf[2] = {bq[nf].x, bq[nf].y};
                    mma_tf32(acc[mf][nf], af, bf);
                }
            }
            #pragma unroll
            for (int mf = 0; mf < 4; mf++) {
                uint32_t af[4] = {aL[mf].z, aH[mf].z, aL[mf].w, aH[mf].w};
                #pragma unroll
                for (int nf = 0; nf < 4; nf++) {
                    uint32_t bf[2] = {bq[nf].z, bq[nf].w};
                    mma_tf32(acc[mf][nf], af, bf);
                }
            }
        }

        __syncthreads();
        if (k + 2 < G_NK) load_stage(s, (k + 2) * G_BK);
        CP_COMMIT();
    }

    #pragma unroll
    for (int mf = 0; mf < 4; mf++) {
        const int r0 = m0 + wm * 64 + mf * 16 + g;
        #pragma unroll
        for (int nf = 0; nf < 4; nf++) {
            const int c0 = n0 + wn * 32 + nf * 8 + 2 * tid4;
            const float b0 = bias[c0], b1 = bias[c0 + 1];
            float v0 = acc[mf][nf][0] + b0, v1 = acc[mf][nf][1] + b1;
            float v2 = acc[mf][nf][2] + b0, v3 = acc[mf][nf][3] + b1;
            if (MODE == 0) {
                *(float2*)(C + (size_t)r0 * Dmod + c0)       = make_float2(v0, v1);
                *(float2*)(C + (size_t)(r0 + 8) * Dmod + c0) = make_float2(v2, v3);
            } else if (MODE == 1) {
                const int bb = r0 >> 11, s = r0 & 2047, hh = c0 >> 7;
                const int j = (c0 & 127) >> 1;
                const int p = (j & ~7) | (2 * tid4 + (nf & 1));
                const size_t base = ((size_t)(bb * Hh + hh) * Sseq + s) * 64 + p;
                uint32_t hi, lo;
                split2(v0, v1, hi, lo);
                Chi[base] = hi; Clo[base] = lo;
                split2(v2, v3, hi, lo);
                Chi[base + 512] = hi; Clo[base + 512] = lo;
            } else {
                float u0 = __shfl_xor_sync(0xFFFFFFFFu, v0, 4);
                float u1 = __shfl_xor_sync(0xFFFFFFFFu, v1, 4);
                float u2 = __shfl_xor_sync(0xFFFFFFFFu, v2, 4);
                float u3 = __shfl_xor_sync(0xFFFFFFFFu, v3, 4);
                if ((g & 1) == 0) {
                    const int bb = r0 >> 11, s = r0 & 2047, hh = c0 >> 7;
                    const int d = c0 & 127;
                    const size_t base0 =
                        ((size_t)(bb * Hh + hh) * DKk + d) * 1024 + ((s & ~15) >> 1);
                    uint32_t hi, lo;
                    split2(v0, u0, hi, lo);
                    Chi[base0 + g] = hi;            Clo[base0 + g] = lo;
                    split2(v2, u2, hi, lo);
                    Chi[base0 + g + 1] = hi;        Clo[base0 + g + 1] = lo;
                    split2(v1, u1, hi, lo);
                    Chi[base0 + 1024 + g] = hi;     Clo[base0 + 1024 + g] = lo;
                    split2(v3, u3, hi, lo);
                    Chi[base0 + 1024 + g + 1] = hi; Clo[base0 + 1024 + g + 1] = lo;
                }
            }
        }
    }
}

// Merged Q/K/V projection (grid.z selects input/weight/epilogue)
__global__ __launch_bounds__(256, 2) void qkv_gemm_kernel(
    const float* __restrict__ Aq, const float* __restrict__ Ak,
    const float* __restrict__ Av,
    const float* __restrict__ WqT, const float* __restrict__ WkT,
    const float* __restrict__ WvT,
    const float* __restrict__ bq, const float* __restrict__ bk,
    const float* __restrict__ bv,
    float* __restrict__ Q,
    uint32_t* __restrict__ Khi, uint32_t* __restrict__ Klo,
    uint32_t* __restrict__ Vhi, uint32_t* __restrict__ Vlo)
{
    extern __shared__ uint32_t smw[];
    const uint32_t smem_base = smem_u32(smw);
    const int m0 = blockIdx.y * 128;
    const int n0 = blockIdx.x * 128;
    const int z = blockIdx.z;
    if (z == 0)
        gemm_body<0>(smw, smem_base, Aq, WqT, bq, Q, nullptr, nullptr, m0, n0);
    else if (z == 1)
        gemm_body<1>(smw, smem_base, Ak, WkT, bk, nullptr, Khi, Klo, m0, n0);
    else
        gemm_body<2>(smw, smem_base, Av, WvT, bv, nullptr, Vhi, Vlo, m0, n0);
}

__global__ __launch_bounds__(256, 2) void o_gemm_kernel(
    const float* __restrict__ A, const float* __restrict__ WT,
    const float* __restrict__ bias, float* __restrict__ C)
{
    extern __shared__ uint32_t smw[];
    const uint32_t smem_base = smem_u32(smw);
    gemm_body<0>(smw, smem_base, A, WT, bias, C, nullptr, nullptr,
                 blockIdx.y * 128, blockIdx.x * 128);
}

// ---------------------------------------------------------------------------
// Tensor-core causal FA (unchanged mainloop; epilogue uses perm16)
// ---------------------------------------------------------------------------
#define KROWW 72
#define VROWW 40
#define FA_STAGE_WORDS (2 * 64 * KROWW + 2 * 128 * VROWW)
#define FA_SMEM_BYTES (2 * FA_STAGE_WORDS * 4)

__global__ __launch_bounds__(256, 1) void fa_tc_kernel(
    const float* __restrict__ Q,
    const uint32_t* __restrict__ KhiG, const uint32_t* __restrict__ KloG,
    const uint32_t* __restrict__ VhiG, const uint32_t* __restrict__ VloG,
    float* __restrict__ Ar)
{
    extern __shared__ uint32_t su[];
    const uint32_t smem_base = smem_u32(su);

    const int qb = (int)gridDim.x - 1 - (int)blockIdx.x;
    const int h  = blockIdx.y;
    const int b  = blockIdx.z;
    const int t  = threadIdx.x;
    const int w  = t >> 5;
    const int lane = t & 31;
    const int g  = lane >> 2;
    const int t4 = lane & 3;
    const int q0 = qb * 128;

    const size_t bh_off = (size_t)b * Sseq * Dmod + (size_t)h * DKk;
    const size_t bhS = (size_t)(b * Hh + h) * Sseq;
    const size_t bhD = (size_t)(b * Hh + h) * DKk;

    const float qscale = 0.088388347648318447f * 1.4426950408889634f;
    uint32_t qhi[8][4], qlo[8][4];
    {
        const float* Qw = Q + bh_off + (size_t)(q0 + w * 16) * Dmod;
        #pragma unroll
        for (int ks = 0; ks < 8; ks++) {
            const int d0 = ks * 16 + 2 * t4;
            float2 x0 = *(const float2*)(Qw + (size_t)g * Dmod + d0);
            float2 x1 = *(const float2*)(Qw + (size_t)(g + 8) * Dmod + d0);
            float2 x2 = *(const float2*)(Qw + (size_t)g * Dmod + d0 + 8);
            float2 x3 = *(const float2*)(Qw + (size_t)(g + 8) * Dmod + d0 + 8);
            split2(x0.x * qscale, x0.y * qscale, qhi[ks][0], qlo[ks][0]);
            split2(x1.x * qscale, x1.y * qscale, qhi[ks][1], qlo[ks][1]);
            split2(x2.x * qscale, x2.y * qscale, qhi[ks][2], qlo[ks][2]);
            split2(x3.x * qscale, x3.y * qscale, qhi[ks][3], qlo[ks][3]);
        }
    }

    auto load_tile = [&](int stage, int kt) {
        const int kv0 = kt * 64;
        const uint32_t sb = smem_base + (uint32_t)stage * FA_STAGE_WORDS * 4;
        const uint32_t kh = sb;
        const uint32_t kl = sb + 64 * KROWW * 4;
        const uint32_t vh = sb + 2 * 64 * KROWW * 4;
        const uint32_t vl = vh + 128 * VROWW * 4;
        #pragma unroll
        for (int i = 0; i < 4; i++) {
            int u = t + i * 256;
            int row = u >> 4, w4 = (u & 15) * 4;
            size_t src = (bhS + kv0 + row) * 64 + w4;
            uint32_t doff = (uint32_t)(row * KROWW + w4) * 4;
            CP_ASYNC16(kh + doff, KhiG + src);
            CP_ASYNC16(kl + doff, KloG + src);
        }
        #pragma unroll
        for (int i = 0; i < 4; i++) {
            int u = t + i * 256;
            int row = u >> 3, w4 = (u & 7) * 4;
            size_t src = (bhD + row) * 1024 + (kv0 >> 1) + w4;
            uint32_t doff = (uint32_t)(row * VROWW + w4) * 4;
            CP_ASYNC16(vh + doff, VhiG + src);
            CP_ASYNC16(vl + doff, VloG + src);
        }
    };

    float oacc[16][4];
    #pragma unroll
    for (int nf = 0; nf < 16; nf++)
        #pragma unroll
        for (int r = 0; r < 4; r++) oacc[nf][r] = 0.f;

    float m0 = -1e30f, m1 = -1e30f, l0 = 0.f, l1 = 0.f;
    const int row0 = q0 + w * 16 + g;
    const int row1 = row0 + 8;

    const int ntiles = 2 * qb + 2;
    load_tile(0, 0);
    CP_COMMIT();

    for (int kt = 0; kt < ntiles; kt++) {
        const int st = kt & 1;
        const int kv0 = kt * 64;
        if (kt + 1 < ntiles) {
            load_tile(st ^ 1, kt + 1);
            CP_COMMIT();
            CP_WAIT(1);
        } else {
            CP_WAIT(0);
        }
        __syncthreads();

        const uint32_t* Khi = su + (size_t)st * FA_STAGE_WORDS;
        const uint32_t* Klo = Khi + 64 * KROWW;
        const uint32_t* Vhi = Khi + 2 * 64 * KROWW;
        const uint32_t* Vlo = Vhi + 128 * VROWW;

        float acc[8][4];
        #pragma unroll
        for (int nf = 0; nf < 8; nf++)
            #pragma unroll
            for (int r = 0; r < 4; r++) acc[nf][r] = 0.f;

        #pragma unroll
        for (int ks = 0; ks < 8; ks++) {
            #pragma unroll
            for (int nf = 0; nf < 8; nf++) {
                const int r = (nf * 8 + g) * KROWW + 8 * ks + 2 * t4;
                uint2 bh = *(const uint2*)&Khi[r];
                uint2 bl = *(const uint2*)&Klo[r];
                mma_bf16(acc[nf], qhi[ks], bh.x, bh.y);
                mma_bf16(acc[nf], qhi[ks], bl.x, bl.y);
                mma_bf16(acc[nf], qlo[ks], bh.x, bh.y);
            }
        }

        if (kv0 + 63 > q0) {
            #pragma unroll
            for (int nf = 0; nf < 8; nf++) {
                const int c = kv0 + nf * 8 + 2 * t4;
                if (c     > row0) acc[nf][0] = -1e30f;
                if (c + 1 > row0) acc[nf][1] = -1e30f;
                if (c     > row1) acc[nf][2] = -1e30f;
                if (c + 1 > row1) acc[nf][3] = -1e30f;
            }
        }

        float mx0 = -1e30f, mx1 = -1e30f;
        #pragma unroll
        for (int nf = 0; nf < 8; nf++) {
            mx0 = fmaxf(mx0, fmaxf(acc[nf][0], acc[nf][1]));
            mx1 = fmaxf(mx1, fmaxf(acc[nf][2], acc[nf][3]));
        }
        mx0 = fmaxf(mx0, __shfl_xor_sync(0xFFFFFFFFu, mx0, 1));
        mx0 = fmaxf(mx0, __shfl_xor_sync(0xFFFFFFFFu, mx0, 2));
        mx1 = fmaxf(mx1, __shfl_xor_sync(0xFFFFFFFFu, mx1, 1));
        mx1 = fmaxf(mx1, __shfl_xor_sync(0xFFFFFFFFu, mx1, 2));

        const float mn0 = fmaxf(m0, mx0);
        const float mn1 = fmaxf(m1, mx1);
        const float cr0 = ex2(m0 - mn0);
        const float cr1 = ex2(m1 - mn1);

        float ps0 = 0.f, ps1 = 0.f;
        #pragma unroll
        for (int nf = 0; nf < 8; nf++) {
            acc[nf][0] = ex2(acc[nf][0] - mn0);
            acc[nf][1] = ex2(acc[nf][1] - mn0);
            acc[nf][2] = ex2(acc[nf][2] - mn1);
            acc[nf][3] = ex2(acc[nf][3] - mn1);
            ps0 += acc[nf][0] + acc[nf][1];
            ps1 += acc[nf][2] + acc[nf][3];
        }
        ps0 += __shfl_xor_sync(0xFFFFFFFFu, ps0, 1);
        ps0 += __shfl_xor_sync(0xFFFFFFFFu, ps0, 2);
        ps1 += __shfl_xor_sync(0xFFFFFFFFu, ps1, 1);
        ps1 += __shfl_xor_sync(0xFFFFFFFFu, ps1, 2);

        l0 = l0 * cr0 + ps0;
        l1 = l1 * cr1 + ps1;
        m0 = mn0;
        m1 = mn1;

        #pragma unroll
        for (int nf = 0; nf < 16; nf++) {
            oacc[nf][0] *= cr0;
            oacc[nf][1] *= cr0;
            oacc[nf][2] *= cr1;
            oacc[nf][3] *= cr1;
        }

        #pragma unroll
        for (int ks2 = 0; ks2 < 4; ks2++) {
            uint32_t ahi[4], alo[4];
            split2(acc[2 * ks2][0],     acc[2 * ks2][1],     ahi[0], alo[0]);
            split2(acc[2 * ks2][2],     acc[2 * ks2][3],     ahi[1], alo[1]);
            split2(acc[2 * ks2 + 1][0], acc[2 * ks2 + 1][1], ahi[2], alo[2]);
            split2(acc[2 * ks2 + 1][2], acc[2 * ks2 + 1][3], ahi[3], alo[3]);
            #pragma unroll
            for (int nf = 0; nf < 16; nf++) {
                const int r = (nf * 8 + g) * VROWW + 8 * ks2 + 2 * t4;
                uint2 bh = *(const uint2*)&Vhi[r];
                uint2 bl = *(const uint2*)&Vlo[r];
                mma_bf16(oacc[nf], ahi, bh.x, bh.y);
                mma_bf16(oacc[nf], ahi, bl.x, bl.y);
                mma_bf16(oacc[nf], alo, bh.x, bh.y);
            }
        }
        __syncthreads();
    }

    // epilogue: normalize, tf32 round, perm16, store into Ar
    const float inv0 = 1.0f / l0;
    const float inv1 = 1.0f / l1;
    float* Ow = Ar + bh_off + (size_t)(q0 + w * 16) * Dmod;
    #pragma unroll
    for (int nf = 0; nf < 16; nf++) {
        const int c = nf * 8 + 2 * t4;
        const int q0i = perm16(c);
        const int q1i = perm16(c + 1);
        Ow[(size_t)g * Dmod + q0i] = __uint_as_float(f2tf32(oacc[nf][0] * inv0));
        Ow[(size_t)g * Dmod + q1i] = __uint_as_float(f2tf32(oacc[nf][1] * inv0));
        Ow[(size_t)(g + 8) * Dmod + q0i] = __uint_as_float(f2tf32(oacc[nf][2] * inv1));
        Ow[(size_t)(g + 8) * Dmod + q1i] = __uint_as_float(f2tf32(oacc[nf][3] * inv1));
    }
}

// ---------------------------------------------------------------------------
// kernel_launch
// ---------------------------------------------------------------------------
extern "C" void kernel_launch(void* const* d_in, const int* in_sizes, int n_in,
                              void* d_out, int out_size)
{
    const float* queries = (const float*)d_in[0];
    const float* keys    = (const float*)d_in[1];
    const float* values  = (const float*)d_in[2];
    const float* Wq      = (const float*)d_in[3];
    const float* bq      = (const float*)d_in[4];
    const float* Wlk     = (const float*)d_in[5];
    const float* blk     = (const float*)d_in[6];
    const float* Wlv     = (const float*)d_in[7];
    const float* blv     = (const float*)d_in[8];
    const float* Wkr     = (const float*)d_in[9];
    const float* bkr     = (const float*)d_in[10];
    const float* Wvr     = (const float*)d_in[11];
    const float* bvr     = (const float*)d_in[12];
    const float* Wo      = (const float*)d_in[13];
    const float* bo      = (const float*)d_in[14];
    float* out = (float*)d_out;

    float *Q, *Ar, *ArK, *ArV, *WqT, *WkT, *WvT, *WoT, *bk, *bv;
    uint32_t *Khi, *Klo, *Vhi, *Vlo;
    cudaGetSymbolAddress((void**)&Q,   g_Q);
    cudaGetSymbolAddress((void**)&Ar,  g_Ar);
    cudaGetSymbolAddress((void**)&ArK, g_ArK);
    cudaGetSymbolAddress((void**)&ArV, g_ArV);
    cudaGetSymbolAddress((void**)&Khi, g_Khi);
    cudaGetSymbolAddress((void**)&Klo, g_Klo);
    cudaGetSymbolAddress((void**)&Vhi, g_Vhi);
    cudaGetSymbolAddress((void**)&Vlo, g_Vlo);
    cudaGetSymbolAddress((void**)&WqT, g_WqT);
    cudaGetSymbolAddress((void**)&WkT, g_WkT);
    cudaGetSymbolAddress((void**)&WvT, g_WvT);
    cudaGetSymbolAddress((void**)&WoT, g_WoT);
    cudaGetSymbolAddress((void**)&bk,  g_bk);
    cudaGetSymbolAddress((void**)&bv,  g_bv);

    cudaFuncSetAttribute(qkv_gemm_kernel,
                         cudaFuncAttributeMaxDynamicSharedMemorySize, G_SMEM_BYTES);
    cudaFuncSetAttribute(o_gemm_kernel,
                         cudaFuncAttributeMaxDynamicSharedMemorySize, G_SMEM_BYTES);
    cudaFuncSetAttribute(fa_tc_kernel,
                         cudaFuncAttributeMaxDynamicSharedMemorySize, FA_SMEM_BYTES);
    cudaFuncSetAttribute(foldT_kernel,
                         cudaFuncAttributeMaxDynamicSharedMemorySize, FT_SMEM_BYTES);

    // Weight preparation (merged launches)
    foldT_kernel<<<dim3(16, 16, 2), 256, FT_SMEM_BYTES>>>(
        Wlk, Wkr, WkT, Wlv, Wvr, WvT);
    fold_b_kernel<<<dim3(Hh, 2), 128>>>(blk, Wkr, bkr, bk, blv, Wvr, bvr, bv);
    transpose_kernel<<<dim3(64, 64, 2), 256>>>(Wq, WqT, Wo, WoT);

    // Round + permute all three activation inputs (merged)
    const int rblocks = (int)(((size_t)Mrows * Dmod / 16) / 256);
    round_perm_kernel<<<dim3(rblocks, 1, 3), 256>>>(
        queries, keys, values, Ar, ArK, ArV);

    // Merged Q/K/V projections
    qkv_gemm_kernel<<<dim3(Dmod / 128, Mrows / 128, 3), 256, G_SMEM_BYTES>>>(
        Ar, ArK, ArV, WqT, WkT, WvT, bq, bk, bv, Q, Khi, Klo, Vhi, Vlo);

    // Fused causal attention (writes rounded+permuted output into Ar)
    fa_tc_kernel<<<dim3(Sseq / 128, Hh, Bsz), 256, FA_SMEM_BYTES>>>(
        Q, Khi, Klo, Vhi, Vlo, Ar);

    // Output projection
    o_gemm_kernel<<<dim3(Dmod / 128, Mrows / 128), 256, G_SMEM_BYTES>>>(
        Ar, WoT, bo, out);
}